// round 1
// baseline (speedup 1.0000x reference)
#include <cuda_runtime.h>
#include <math.h>

#define S_TOK 8192
#define MDIM  1024
#define HDIM  2048
#define EDIM  8
#define CDIM  2048

// ---------------- scratch (device globals; no allocation) ----------------
__device__ int   g_topi[S_TOK * 2];
__device__ float g_gate[S_TOK * 2];
__device__ int   g_dexp[S_TOK * 2];
__device__ int   g_dpos[S_TOK * 2];
__device__ float g_dg  [S_TOK * 2];
__device__ int   g_src [EDIM * CDIM];
__device__ float g_z   [EDIM * CDIM];
__device__ float g_w2s [EDIM * HDIM];
__device__ float g_b2s [EDIM];

// ---------------- 1. router: logits -> softmax -> top2 -> gates ----------
__global__ void routing_kernel(const float* __restrict__ x,
                               const float* __restrict__ wg) {
    int warp = (blockIdx.x * blockDim.x + threadIdx.x) >> 5;
    int lane = threadIdx.x & 31;
    if (warp >= S_TOK) return;
    const float* xr = x + (size_t)warp * MDIM;
    float acc[8];
#pragma unroll
    for (int e = 0; e < 8; e++) acc[e] = 0.f;
    for (int m = lane; m < MDIM; m += 32) {
        float xv = xr[m];
        const float* wr = wg + m * 8;
        float4 w0 = *(const float4*)(wr);
        float4 w1 = *(const float4*)(wr + 4);
        acc[0] += xv * w0.x; acc[1] += xv * w0.y;
        acc[2] += xv * w0.z; acc[3] += xv * w0.w;
        acc[4] += xv * w1.x; acc[5] += xv * w1.y;
        acc[6] += xv * w1.z; acc[7] += xv * w1.w;
    }
#pragma unroll
    for (int off = 16; off > 0; off >>= 1)
#pragma unroll
        for (int e = 0; e < 8; e++)
            acc[e] += __shfl_down_sync(0xffffffffu, acc[e], off);
    if (lane == 0) {
        float mx = acc[0];
#pragma unroll
        for (int e = 1; e < 8; e++) mx = fmaxf(mx, acc[e]);
        float sc[8], s = 0.f;
#pragma unroll
        for (int e = 0; e < 8; e++) { sc[e] = expf(acc[e] - mx); s += sc[e]; }
        float inv = 1.f / s;
#pragma unroll
        for (int e = 0; e < 8; e++) sc[e] *= inv;
        // top-2, ties -> lowest index first (strict > keeps first occurrence)
        int i0 = 0;
#pragma unroll
        for (int e = 1; e < 8; e++) if (sc[e] > sc[i0]) i0 = e;
        int i1 = -1;
#pragma unroll
        for (int e = 0; e < 8; e++) {
            if (e == i0) continue;
            if (i1 < 0 || sc[e] > sc[i1]) i1 = e;
        }
        float v0 = sc[i0], v1 = sc[i1];
        float den = 1.f / (v0 + v1 + 1e-9f);
        g_topi[warp * 2 + 0] = i0;
        g_topi[warp * 2 + 1] = i1;
        g_gate[warp * 2 + 0] = v0 * den;
        g_gate[warp * 2 + 1] = v1 * den;
    }
}

// ---------------- 2. ordered scan: positions, keep, inverse index --------
// Single block, 256 threads, 32 tokens each, token order preserved.
__global__ void scan_kernel() {
    __shared__ int h0[256][8];
    __shared__ int h1[256][8];
    __shared__ int tot0[8];
    int t = threadIdx.x;
    // zero z + init src
    for (int i = t; i < EDIM * CDIM; i += 256) { g_src[i] = -1; g_z[i] = 0.f; }

    int c0[8], c1[8];
#pragma unroll
    for (int e = 0; e < 8; e++) { c0[e] = 0; c1[e] = 0; }
    int base = t * 32;
    for (int k = 0; k < 32; k++) {
        int s = base + k;
        c0[g_topi[2 * s + 0]]++;
        c1[g_topi[2 * s + 1]]++;
    }
#pragma unroll
    for (int e = 0; e < 8; e++) { h0[t][e] = c0[e]; h1[t][e] = c1[e]; }
    __syncthreads();
    // 16 threads: sequential exclusive scan per (slot, expert) bin
    if (t < 16) {
        int e = t & 7, which = t >> 3;
        int run = 0;
        if (which == 0) {
            for (int i = 0; i < 256; i++) { int v = h0[i][e]; h0[i][e] = run; run += v; }
            tot0[e] = run;
        } else {
            for (int i = 0; i < 256; i++) { int v = h1[i][e]; h1[i][e] = run; run += v; }
        }
    }
    __syncthreads();
#pragma unroll
    for (int e = 0; e < 8; e++) { c0[e] = h0[t][e]; c1[e] = h1[t][e] + tot0[e]; }
    for (int k = 0; k < 32; k++) {
        int s = base + k;
        // slot 0
        {
            int e = g_topi[2 * s + 0];
            int pos = c0[e]++;
            int keep = (pos < CDIM);
            int posc = keep ? pos : (CDIM - 1);
            g_dexp[2 * s + 0] = e;
            g_dpos[2 * s + 0] = posc;
            g_dg  [2 * s + 0] = keep ? g_gate[2 * s + 0] : 0.f;
            if (keep) g_src[e * CDIM + posc] = s;
        }
        // slot 1 (offset by slot-0 totals)
        {
            int e = g_topi[2 * s + 1];
            int pos = c1[e]++;
            int keep = (pos < CDIM);
            int posc = keep ? pos : (CDIM - 1);
            g_dexp[2 * s + 1] = e;
            g_dpos[2 * s + 1] = posc;
            g_dg  [2 * s + 1] = keep ? g_gate[2 * s + 1] : 0.f;
            if (keep) g_src[e * CDIM + posc] = s;
        }
    }
}

// ---------------- 3. w2s[e,h] = sum_m w2[e,h,m]; b2s[e] = sum_m b2[e,m] --
__global__ void w2s_kernel(const float* __restrict__ w2,
                           const float* __restrict__ b2) {
    int warp = (blockIdx.x * blockDim.x + threadIdx.x) >> 5;
    int lane = threadIdx.x & 31;
    if (warp < EDIM * HDIM) {
        const float4* r = (const float4*)(w2 + (size_t)warp * MDIM);
        float s = 0.f;
        for (int m = lane; m < MDIM / 4; m += 32) {
            float4 v = r[m];
            s += v.x + v.y + v.z + v.w;
        }
#pragma unroll
        for (int off = 16; off > 0; off >>= 1) s += __shfl_down_sync(0xffffffffu, s, off);
        if (lane == 0) g_w2s[warp] = s;
    } else if (warp < EDIM * HDIM + EDIM) {
        int e = warp - EDIM * HDIM;
        const float4* r = (const float4*)(b2 + (size_t)e * MDIM);
        float s = 0.f;
        for (int m = lane; m < MDIM / 4; m += 32) {
            float4 v = r[m];
            s += v.x + v.y + v.z + v.w;
        }
#pragma unroll
        for (int off = 16; off > 0; off >>= 1) s += __shfl_down_sync(0xffffffffu, s, off);
        if (lane == 0) g_b2s[e] = s;
    }
}

// ---------------- 4. fused GEMM: z[e,c] = relu(gather(x)@w1 + b1) . w2s --
#define BM 128
#define BN 128
#define BK 16

__global__ __launch_bounds__(256, 2)
void moe_gemm_kernel(const float* __restrict__ x,
                     const float* __restrict__ w1,
                     const float* __restrict__ b1) {
    __shared__ float As[BK][BM];
    __shared__ float Bs[BK][BN];
    __shared__ int   rowsrc[BM];
    __shared__ float red[16][BM];

    int e  = blockIdx.z;
    int cb = blockIdx.y * BM;
    int nb = blockIdx.x * BN;
    int tid = threadIdx.x;

    if (tid < BM) rowsrc[tid] = g_src[e * CDIM + cb + tid];
    __syncthreads();

    int tr = tid >> 4;          // 0..15 -> rows tr*8..tr*8+7
    int tc = tid & 15;          // 0..15 -> cols tc*8..tc*8+7

    float acc[8][8];
#pragma unroll
    for (int i = 0; i < 8; i++)
#pragma unroll
        for (int j = 0; j < 8; j++) acc[i][j] = 0.f;

    int aRow = tid >> 2;              // 0..63 (+64)
    int aK   = (tid & 3) * 4;
    int bRow = tid >> 5;              // 0..7 (+8)
    int bCol = (tid & 31) * 4;
    const float* w1e = w1 + (size_t)e * MDIM * HDIM + nb;

    // prefetch first k-tile
    float4 va[2], vb[2];
#pragma unroll
    for (int rr = 0; rr < 2; rr++) {
        int s = rowsrc[aRow + rr * 64];
        va[rr] = (s >= 0) ? *(const float4*)(x + (size_t)s * MDIM + aK)
                          : make_float4(0.f, 0.f, 0.f, 0.f);
        vb[rr] = *(const float4*)(w1e + (size_t)(bRow + rr * 8) * HDIM + bCol);
    }

    for (int k0 = 0; k0 < MDIM; k0 += BK) {
#pragma unroll
        for (int rr = 0; rr < 2; rr++) {
            int row = aRow + rr * 64;
            As[aK + 0][row] = va[rr].x;
            As[aK + 1][row] = va[rr].y;
            As[aK + 2][row] = va[rr].z;
            As[aK + 3][row] = va[rr].w;
            *(float4*)&Bs[bRow + rr * 8][bCol] = vb[rr];
        }
        __syncthreads();
        // prefetch next k-tile (latency hidden behind compute)
        if (k0 + BK < MDIM) {
            int kn = k0 + BK;
#pragma unroll
            for (int rr = 0; rr < 2; rr++) {
                int s = rowsrc[aRow + rr * 64];
                va[rr] = (s >= 0) ? *(const float4*)(x + (size_t)s * MDIM + kn + aK)
                                  : make_float4(0.f, 0.f, 0.f, 0.f);
                vb[rr] = *(const float4*)(w1e + (size_t)(kn + bRow + rr * 8) * HDIM + bCol);
            }
        }
#pragma unroll
        for (int kk = 0; kk < BK; kk++) {
            float ra[8], rb[8];
            *(float4*)&ra[0] = *(const float4*)&As[kk][tr * 8];
            *(float4*)&ra[4] = *(const float4*)&As[kk][tr * 8 + 4];
            *(float4*)&rb[0] = *(const float4*)&Bs[kk][tc * 8];
            *(float4*)&rb[4] = *(const float4*)&Bs[kk][tc * 8 + 4];
#pragma unroll
            for (int i = 0; i < 8; i++)
#pragma unroll
                for (int j = 0; j < 8; j++)
                    acc[i][j] += ra[i] * rb[j];
        }
        __syncthreads();
    }

    // epilogue: +b1, relu, dot with w2s -> per-row partial
    float partial[8];
#pragma unroll
    for (int i = 0; i < 8; i++) partial[i] = 0.f;
#pragma unroll
    for (int j = 0; j < 8; j++) {
        int n = nb + tc * 8 + j;
        float bb = b1[e * HDIM + n];
        float ws = g_w2s[e * HDIM + n];
#pragma unroll
        for (int i = 0; i < 8; i++) {
            float hv = fmaxf(acc[i][j] + bb, 0.f);
            partial[i] += hv * ws;
        }
    }
#pragma unroll
    for (int i = 0; i < 8; i++) red[tc][tr * 8 + i] = partial[i];
    __syncthreads();
    if (tid < BM) {
        float s = 0.f;
#pragma unroll
        for (int c = 0; c < 16; c++) s += red[c][tid];
        atomicAdd(&g_z[e * CDIM + cb + tid], s);
    }
}

// ---------------- 5. combine: per-token scalar -----------------------
__global__ void combine_kernel(float* __restrict__ out) {
    int s = blockIdx.x * blockDim.x + threadIdx.x;
    if (s >= S_TOK) return;
    float v = 0.f;
#pragma unroll
    for (int j = 0; j < 2; j++) {
        int   e = g_dexp[2 * s + j];
        int   p = g_dpos[2 * s + j];
        float g = g_dg  [2 * s + j];
        v += g * (g_z[e * CDIM + p] + g_b2s[e]);
    }
    out[s] = v;
}

// ---------------- 6. log_softmax over T (per batch), in place ---------
__global__ void lsm_kernel(float* __restrict__ out) {
    __shared__ float sred[256];
    int t = threadIdx.x;
    float* v = out + (size_t)blockIdx.x * 2048;
    float mx = -1e30f;
    for (int i = t; i < 2048; i += 256) mx = fmaxf(mx, v[i]);
    sred[t] = mx; __syncthreads();
    for (int o = 128; o > 0; o >>= 1) {
        if (t < o) sred[t] = fmaxf(sred[t], sred[t + o]);
        __syncthreads();
    }
    mx = sred[0]; __syncthreads();
    float sm = 0.f;
    for (int i = t; i < 2048; i += 256) sm += expf(v[i] - mx);
    sred[t] = sm; __syncthreads();
    for (int o = 128; o > 0; o >>= 1) {
        if (t < o) sred[t] += sred[t + o];
        __syncthreads();
    }
    float lse = mx + logf(sred[0]);
    for (int i = t; i < 2048; i += 256) v[i] = v[i] - lse;
}

// ---------------- launch ----------------------------------------------
extern "C" void kernel_launch(void* const* d_in, const int* in_sizes, int n_in,
                              void* d_out, int out_size) {
    const float* x  = (const float*)d_in[0];
    const float* wg = (const float*)d_in[1];
    const float* w1 = (const float*)d_in[2];
    const float* b1 = (const float*)d_in[3];
    const float* w2 = (const float*)d_in[4];
    const float* b2 = (const float*)d_in[5];
    float* out = (float*)d_out;

    routing_kernel<<<S_TOK / 8, 256>>>(x, wg);          // warp per token
    scan_kernel<<<1, 256>>>();                           // ordered capacity scan
    w2s_kernel<<<(EDIM * HDIM + EDIM + 7) / 8, 256>>>(w2, b2);
    moe_gemm_kernel<<<dim3(HDIM / BN, CDIM / BM, EDIM), 256>>>(x, w1, b1);
    combine_kernel<<<S_TOK / 256, 256>>>(out);
    lsm_kernel<<<4, 256>>>(out);
}

// round 3
// speedup vs baseline: 2.1942x; 2.1942x over previous
#include <cuda_runtime.h>
#include <cuda_bf16.h>
#include <math.h>
#include <stdint.h>

#define S_TOK 8192
#define MDIM  1024
#define HDIM  2048
#define EDIM  8
#define CDIM  2048

// ---------------- scratch (device globals; no allocation) ----------------
__device__ int   g_topi[S_TOK * 2];
__device__ float g_gate[S_TOK * 2];
__device__ int   g_dexp[S_TOK * 2];
__device__ int   g_dpos[S_TOK * 2];
__device__ float g_dg  [S_TOK * 2];
__device__ int   g_src [EDIM * CDIM];
__device__ float g_z   [EDIM * CDIM];
__device__ float g_w2s [EDIM * HDIM];
__device__ float g_b2s [EDIM];
// bf16 hi/lo splits
__device__ __nv_bfloat16 g_xhi [(size_t)S_TOK * MDIM];
__device__ __nv_bfloat16 g_xlo [(size_t)S_TOK * MDIM];
__device__ __nv_bfloat16 g_w1hi[(size_t)EDIM * MDIM * HDIM];
__device__ __nv_bfloat16 g_w1lo[(size_t)EDIM * MDIM * HDIM];

// ---------------- helpers -------------------------------------------------
__device__ __forceinline__ uint32_t smem_u32(const void* p) {
    uint32_t a;
    asm("{ .reg .u64 t; cvta.to.shared.u64 t, %1; cvt.u32.u64 %0, t; }"
        : "=r"(a) : "l"(p));
    return a;
}
#define CP_ASYNC(saddr, gptr) \
    asm volatile("cp.async.cg.shared.global [%0], [%1], 16;" \
        :: "r"(saddr), "l"(gptr) : "memory")
#define CP_ASYNC_Z(saddr, gptr, srcsz) \
    asm volatile("cp.async.cg.shared.global [%0], [%1], 16, %2;" \
        :: "r"(saddr), "l"(gptr), "r"(srcsz) : "memory")
#define CP_COMMIT() asm volatile("cp.async.commit_group;" ::: "memory")
#define CP_WAIT(n)  asm volatile("cp.async.wait_group %0;" :: "n"(n) : "memory")

#define LDSM4(r, addr) \
    asm volatile("ldmatrix.sync.aligned.m8n8.x4.shared.b16 {%0,%1,%2,%3}, [%4];" \
        : "=r"((r)[0]), "=r"((r)[1]), "=r"((r)[2]), "=r"((r)[3]) : "r"(addr))
#define LDSM4T(r, addr) \
    asm volatile("ldmatrix.sync.aligned.m8n8.x4.trans.shared.b16 {%0,%1,%2,%3}, [%4];" \
        : "=r"((r)[0]), "=r"((r)[1]), "=r"((r)[2]), "=r"((r)[3]) : "r"(addr))
#define MMA_BF16(d, a, b0, b1) \
    asm volatile("mma.sync.aligned.m16n8k16.row.col.f32.bf16.bf16.f32 " \
        "{%0,%1,%2,%3}, {%4,%5,%6,%7}, {%8,%9}, {%0,%1,%2,%3};" \
        : "+f"((d)[0]), "+f"((d)[1]), "+f"((d)[2]), "+f"((d)[3]) \
        : "r"((a)[0]), "r"((a)[1]), "r"((a)[2]), "r"((a)[3]), "r"(b0), "r"(b1))

// ---------------- 1. router -----------------------------------------------
__global__ void routing_kernel(const float* __restrict__ x,
                               const float* __restrict__ wg) {
    int warp = (blockIdx.x * blockDim.x + threadIdx.x) >> 5;
    int lane = threadIdx.x & 31;
    if (warp >= S_TOK) return;
    const float* xr = x + (size_t)warp * MDIM;
    float acc[8];
#pragma unroll
    for (int e = 0; e < 8; e++) acc[e] = 0.f;
    for (int m = lane; m < MDIM; m += 32) {
        float xv = xr[m];
        const float* wr = wg + m * 8;
        float4 w0 = *(const float4*)(wr);
        float4 w1 = *(const float4*)(wr + 4);
        acc[0] += xv * w0.x; acc[1] += xv * w0.y;
        acc[2] += xv * w0.z; acc[3] += xv * w0.w;
        acc[4] += xv * w1.x; acc[5] += xv * w1.y;
        acc[6] += xv * w1.z; acc[7] += xv * w1.w;
    }
#pragma unroll
    for (int off = 16; off > 0; off >>= 1)
#pragma unroll
        for (int e = 0; e < 8; e++)
            acc[e] += __shfl_down_sync(0xffffffffu, acc[e], off);
    if (lane == 0) {
        float mx = acc[0];
#pragma unroll
        for (int e = 1; e < 8; e++) mx = fmaxf(mx, acc[e]);
        float sc[8], s = 0.f;
#pragma unroll
        for (int e = 0; e < 8; e++) { sc[e] = expf(acc[e] - mx); s += sc[e]; }
        float inv = 1.f / s;
#pragma unroll
        for (int e = 0; e < 8; e++) sc[e] *= inv;
        int i0 = 0;
#pragma unroll
        for (int e = 1; e < 8; e++) if (sc[e] > sc[i0]) i0 = e;
        int i1 = -1;
#pragma unroll
        for (int e = 0; e < 8; e++) {
            if (e == i0) continue;
            if (i1 < 0 || sc[e] > sc[i1]) i1 = e;
        }
        float v0 = sc[i0], v1 = sc[i1];
        float den = 1.f / (v0 + v1 + 1e-9f);
        g_topi[warp * 2 + 0] = i0;
        g_topi[warp * 2 + 1] = i1;
        g_gate[warp * 2 + 0] = v0 * den;
        g_gate[warp * 2 + 1] = v1 * den;
    }
}

// ---------------- 2. ordered scan -----------------------------------------
__global__ void scan_kernel() {
    __shared__ int h0[256][8];
    __shared__ int h1[256][8];
    __shared__ int tot0[8];
    int t = threadIdx.x;
    for (int i = t; i < EDIM * CDIM; i += 256) { g_src[i] = -1; g_z[i] = 0.f; }

    int c0[8], c1[8];
#pragma unroll
    for (int e = 0; e < 8; e++) { c0[e] = 0; c1[e] = 0; }
    int base = t * 32;
    for (int k = 0; k < 32; k++) {
        int s = base + k;
        c0[g_topi[2 * s + 0]]++;
        c1[g_topi[2 * s + 1]]++;
    }
#pragma unroll
    for (int e = 0; e < 8; e++) { h0[t][e] = c0[e]; h1[t][e] = c1[e]; }
    __syncthreads();
    if (t < 16) {
        int e = t & 7, which = t >> 3;
        int run = 0;
        if (which == 0) {
            for (int i = 0; i < 256; i++) { int v = h0[i][e]; h0[i][e] = run; run += v; }
            tot0[e] = run;
        } else {
            for (int i = 0; i < 256; i++) { int v = h1[i][e]; h1[i][e] = run; run += v; }
        }
    }
    __syncthreads();
#pragma unroll
    for (int e = 0; e < 8; e++) { c0[e] = h0[t][e]; c1[e] = h1[t][e] + tot0[e]; }
    for (int k = 0; k < 32; k++) {
        int s = base + k;
        {
            int e = g_topi[2 * s + 0];
            int pos = c0[e]++;
            int keep = (pos < CDIM);
            int posc = keep ? pos : (CDIM - 1);
            g_dexp[2 * s + 0] = e;
            g_dpos[2 * s + 0] = posc;
            g_dg  [2 * s + 0] = keep ? g_gate[2 * s + 0] : 0.f;
            if (keep) g_src[e * CDIM + posc] = s;
        }
        {
            int e = g_topi[2 * s + 1];
            int pos = c1[e]++;
            int keep = (pos < CDIM);
            int posc = keep ? pos : (CDIM - 1);
            g_dexp[2 * s + 1] = e;
            g_dpos[2 * s + 1] = posc;
            g_dg  [2 * s + 1] = keep ? g_gate[2 * s + 1] : 0.f;
            if (keep) g_src[e * CDIM + posc] = s;
        }
    }
}

// ---------------- 3. w2s / b2s reductions ---------------------------------
__global__ void w2s_kernel(const float* __restrict__ w2,
                           const float* __restrict__ b2) {
    int warp = (blockIdx.x * blockDim.x + threadIdx.x) >> 5;
    int lane = threadIdx.x & 31;
    if (warp < EDIM * HDIM) {
        const float4* r = (const float4*)(w2 + (size_t)warp * MDIM);
        float s = 0.f;
        for (int m = lane; m < MDIM / 4; m += 32) {
            float4 v = r[m];
            s += v.x + v.y + v.z + v.w;
        }
#pragma unroll
        for (int off = 16; off > 0; off >>= 1) s += __shfl_down_sync(0xffffffffu, s, off);
        if (lane == 0) g_w2s[warp] = s;
    } else if (warp < EDIM * HDIM + EDIM) {
        int e = warp - EDIM * HDIM;
        const float4* r = (const float4*)(b2 + (size_t)e * MDIM);
        float s = 0.f;
        for (int m = lane; m < MDIM / 4; m += 32) {
            float4 v = r[m];
            s += v.x + v.y + v.z + v.w;
        }
#pragma unroll
        for (int off = 16; off > 0; off >>= 1) s += __shfl_down_sync(0xffffffffu, s, off);
        if (lane == 0) g_b2s[e] = s;
    }
}

// ---------------- 3b. hi/lo split (x and w1, same layout) -----------------
__global__ void split_kernel(const float* __restrict__ src,
                             __nv_bfloat16* __restrict__ hi,
                             __nv_bfloat16* __restrict__ lo, int n4) {
    int i = blockIdx.x * blockDim.x + threadIdx.x;
    if (i >= n4) return;
    float4 v = ((const float4*)src)[i];
    __nv_bfloat162 h01 = __floats2bfloat162_rn(v.x, v.y);
    __nv_bfloat162 h23 = __floats2bfloat162_rn(v.z, v.w);
    float2 f01 = __bfloat1622float2(h01);
    float2 f23 = __bfloat1622float2(h23);
    __nv_bfloat162 l01 = __floats2bfloat162_rn(v.x - f01.x, v.y - f01.y);
    __nv_bfloat162 l23 = __floats2bfloat162_rn(v.z - f23.x, v.w - f23.y);
    ((uint2*)hi)[i] = make_uint2(*(uint32_t*)&h01, *(uint32_t*)&h23);
    ((uint2*)lo)[i] = make_uint2(*(uint32_t*)&l01, *(uint32_t*)&l23);
}

// ---------------- 4. mma.sync fused GEMM ----------------------------------
// CTA tile 128(C) x 128(H), BK=32, 3-stage cp.async pipeline.
// A (gathered x rows) padded 80B rows; B rows 256B with XOR-8 swizzle.
#define NS   3
#define AHI  0
#define ALO  10240
#define BHI  20480
#define BLO  28672
#define STG  36864
#define GEMM_SMEM (NS * STG)

__global__ __launch_bounds__(256, 1)
void moe_gemm_mma(const float* __restrict__ b1) {
    extern __shared__ char smem[];
    __shared__ int   rowsrc[128];
    __shared__ float b1s[128];
    __shared__ float w2ss[128];

    const int tid  = threadIdx.x;
    const int lane = tid & 31;
    const int wid  = tid >> 5;
    const int e  = blockIdx.z;
    const int cb = blockIdx.y * 128;
    const int nb = blockIdx.x * 128;

    if (tid < 128) {
        rowsrc[tid] = g_src[e * CDIM + cb + tid];
        b1s[tid]  = b1[e * HDIM + nb + tid];
        w2ss[tid] = g_w2s[e * HDIM + nb + tid];
    }
    __syncthreads();
    const uint32_t sb = smem_u32(smem);

    // ---- cp.async assignments ----
    // A: thread covers rows ar, ar+64, 16B unit au (k-cols au*8..au*8+7)
    const int ar = tid >> 2, au = tid & 3;
    const int s0 = rowsrc[ar], s1 = rowsrc[ar + 64];
    const uint32_t sz0 = (s0 >= 0) ? 16u : 0u;
    const uint32_t sz1 = (s1 >= 0) ? 16u : 0u;
    const char* gxh0 = (const char*)g_xhi + ((size_t)(s0 < 0 ? 0 : s0) * MDIM + au * 8) * 2;
    const char* gxh1 = (const char*)g_xhi + ((size_t)(s1 < 0 ? 0 : s1) * MDIM + au * 8) * 2;
    const char* gxl0 = (const char*)g_xlo + ((size_t)(s0 < 0 ? 0 : s0) * MDIM + au * 8) * 2;
    const char* gxl1 = (const char*)g_xlo + ((size_t)(s1 < 0 ? 0 : s1) * MDIM + au * 8) * 2;
    const uint32_t aoff0 = (uint32_t)(ar * 80 + au * 16);
    const uint32_t aoff1 = (uint32_t)((ar + 64) * 80 + au * 16);
    // B: thread covers k-rows br, br+16, unit bu (n-cols bu*8..bu*8+7)
    const int br = tid >> 4, bu = tid & 15;
    const char* gbh = (const char*)g_w1hi + (((size_t)e * MDIM) * HDIM + nb + bu * 8) * 2;
    const char* gbl = (const char*)g_w1lo + (((size_t)e * MDIM) * HDIM + nb + bu * 8) * 2;
    const uint32_t sB0 = (uint32_t)(br * 256 + ((bu ^ (br & 7)) << 4));
    const uint32_t sB1 = sB0 + 16 * 256;

#define LOAD_STAGE(i) do {                                                    \
    const int _k0 = (i) * 32;                                                 \
    const uint32_t _st = sb + ((i) % NS) * STG;                               \
    CP_ASYNC_Z(_st + AHI + aoff0, gxh0 + _k0 * 2, sz0);                       \
    CP_ASYNC_Z(_st + AHI + aoff1, gxh1 + _k0 * 2, sz1);                       \
    CP_ASYNC_Z(_st + ALO + aoff0, gxl0 + _k0 * 2, sz0);                       \
    CP_ASYNC_Z(_st + ALO + aoff1, gxl1 + _k0 * 2, sz1);                       \
    const size_t _g = (size_t)(_k0 + br) * (HDIM * 2);                        \
    CP_ASYNC(_st + BHI + sB0, gbh + _g);                                      \
    CP_ASYNC(_st + BHI + sB1, gbh + _g + (size_t)16 * HDIM * 2);              \
    CP_ASYNC(_st + BLO + sB0, gbl + _g);                                      \
    CP_ASYNC(_st + BLO + sB1, gbl + _g + (size_t)16 * HDIM * 2);              \
    CP_COMMIT();                                                              \
} while (0)

    // ---- mma thread geometry ----
    const int m0 = (wid & 1) * 64;      // warp row block within CTA
    const int n0 = (wid >> 1) * 32;     // warp col block
    // A ldmatrix per-thread base: row (lane&15), kchunk (lane>>4)
    const uint32_t a_l = (uint32_t)((m0 + (lane & 15)) * 80 + ((lane >> 4) & 1) * 16);
    // B ldmatrix: krow (lane&15), unit base
    const int krow = lane & 15;
    const int un0  = (n0 >> 3) + (lane >> 4);
    const uint32_t b_row = (uint32_t)(krow * 256);
    const uint32_t bcol0 = (uint32_t)(((un0 + 0) ^ (krow & 7)) << 4);
    const uint32_t bcol1 = (uint32_t)(((un0 + 2) ^ (krow & 7)) << 4);

    float acc[4][4][4];
#pragma unroll
    for (int mi = 0; mi < 4; mi++)
#pragma unroll
        for (int nj = 0; nj < 4; nj++)
#pragma unroll
            for (int q = 0; q < 4; q++) acc[mi][nj][q] = 0.f;

    LOAD_STAGE(0);
    LOAD_STAGE(1);

    for (int i = 0; i < 32; i++) {
        CP_WAIT(1);
        __syncthreads();
        if (i + 2 < 32) LOAD_STAGE(i + 2); else CP_COMMIT();

        const uint32_t st = sb + (i % NS) * STG;
        const uint32_t abh = st + AHI + a_l;
        const uint32_t abl = st + ALO + a_l;
        const uint32_t bbh = st + BHI + b_row;
        const uint32_t bbl = st + BLO + b_row;
#pragma unroll
        for (int kk = 0; kk < 2; kk++) {
            uint32_t ahi[4][4], alo[4][4], bhi[2][4], blo[2][4];
#pragma unroll
            for (int mi = 0; mi < 4; mi++)
                LDSM4(ahi[mi], abh + mi * (16 * 80) + kk * 32);
            {
                uint32_t kb = (uint32_t)(kk * 16 * 256);
                LDSM4T(bhi[0], bbh + kb + bcol0);
                LDSM4T(bhi[1], bbh + kb + bcol1);
            }
#pragma unroll
            for (int mi = 0; mi < 4; mi++)
#pragma unroll
                for (int nj = 0; nj < 2; nj++) {
                    MMA_BF16(acc[mi][nj * 2 + 0], ahi[mi], bhi[nj][0], bhi[nj][1]);
                    MMA_BF16(acc[mi][nj * 2 + 1], ahi[mi], bhi[nj][2], bhi[nj][3]);
                }
            {
                uint32_t kb = (uint32_t)(kk * 16 * 256);
                LDSM4T(blo[0], bbl + kb + bcol0);
                LDSM4T(blo[1], bbl + kb + bcol1);
            }
#pragma unroll
            for (int mi = 0; mi < 4; mi++)
#pragma unroll
                for (int nj = 0; nj < 2; nj++) {
                    MMA_BF16(acc[mi][nj * 2 + 0], ahi[mi], blo[nj][0], blo[nj][1]);
                    MMA_BF16(acc[mi][nj * 2 + 1], ahi[mi], blo[nj][2], blo[nj][3]);
                }
#pragma unroll
            for (int mi = 0; mi < 4; mi++)
                LDSM4(alo[mi], abl + mi * (16 * 80) + kk * 32);
#pragma unroll
            for (int mi = 0; mi < 4; mi++)
#pragma unroll
                for (int nj = 0; nj < 2; nj++) {
                    MMA_BF16(acc[mi][nj * 2 + 0], alo[mi], bhi[nj][0], bhi[nj][1]);
                    MMA_BF16(acc[mi][nj * 2 + 1], alo[mi], bhi[nj][2], bhi[nj][3]);
                }
        }
    }

    // ---- fused epilogue: relu(+b1) . w2s, reduce, atomicAdd into g_z ----
    const int rr = lane >> 2;           // row within 16-row frag
    const int cc = (lane & 3) * 2;      // col pair base within 8-col frag
#pragma unroll
    for (int mi = 0; mi < 4; mi++) {
        float pl = 0.f, ph = 0.f;
#pragma unroll
        for (int nj = 0; nj < 4; nj++) {
            int col = n0 + nj * 8 + cc;
            float w0 = w2ss[col], w1v = w2ss[col + 1];
            float bb0 = b1s[col], bb1 = b1s[col + 1];
            pl += fmaxf(acc[mi][nj][0] + bb0, 0.f) * w0
                + fmaxf(acc[mi][nj][1] + bb1, 0.f) * w1v;
            ph += fmaxf(acc[mi][nj][2] + bb0, 0.f) * w0
                + fmaxf(acc[mi][nj][3] + bb1, 0.f) * w1v;
        }
        pl += __shfl_xor_sync(0xffffffffu, pl, 1);
        pl += __shfl_xor_sync(0xffffffffu, pl, 2);
        ph += __shfl_xor_sync(0xffffffffu, ph, 1);
        ph += __shfl_xor_sync(0xffffffffu, ph, 2);
        if ((lane & 3) == 0) {
            int row = cb + m0 + mi * 16 + rr;
            atomicAdd(&g_z[e * CDIM + row], pl);
            atomicAdd(&g_z[e * CDIM + row + 8], ph);
        }
    }
#undef LOAD_STAGE
}

// ---------------- 5. combine ----------------------------------------------
__global__ void combine_kernel(float* __restrict__ out) {
    int s = blockIdx.x * blockDim.x + threadIdx.x;
    if (s >= S_TOK) return;
    float v = 0.f;
#pragma unroll
    for (int j = 0; j < 2; j++) {
        int   e = g_dexp[2 * s + j];
        int   p = g_dpos[2 * s + j];
        float g = g_dg  [2 * s + j];
        v += g * (g_z[e * CDIM + p] + g_b2s[e]);
    }
    out[s] = v;
}

// ---------------- 6. log_softmax over T -----------------------------------
__global__ void lsm_kernel(float* __restrict__ out) {
    __shared__ float sred[256];
    int t = threadIdx.x;
    float* v = out + (size_t)blockIdx.x * 2048;
    float mx = -1e30f;
    for (int i = t; i < 2048; i += 256) mx = fmaxf(mx, v[i]);
    sred[t] = mx; __syncthreads();
    for (int o = 128; o > 0; o >>= 1) {
        if (t < o) sred[t] = fmaxf(sred[t], sred[t + o]);
        __syncthreads();
    }
    mx = sred[0]; __syncthreads();
    float sm = 0.f;
    for (int i = t; i < 2048; i += 256) sm += expf(v[i] - mx);
    sred[t] = sm; __syncthreads();
    for (int o = 128; o > 0; o >>= 1) {
        if (t < o) sred[t] += sred[t + o];
        __syncthreads();
    }
    float lse = mx + logf(sred[0]);
    for (int i = t; i < 2048; i += 256) v[i] = v[i] - lse;
}

// ---------------- launch ---------------------------------------------------
extern "C" void kernel_launch(void* const* d_in, const int* in_sizes, int n_in,
                              void* d_out, int out_size) {
    const float* x  = (const float*)d_in[0];
    const float* wg = (const float*)d_in[1];
    const float* w1 = (const float*)d_in[2];
    const float* b1 = (const float*)d_in[3];
    const float* w2 = (const float*)d_in[4];
    const float* b2 = (const float*)d_in[5];
    float* out = (float*)d_out;

    routing_kernel<<<S_TOK / 8, 256>>>(x, wg);
    scan_kernel<<<1, 256>>>();

    {   // split x and w1 into bf16 hi/lo
        __nv_bfloat16 *xhi, *xlo, *whi, *wlo;
        cudaGetSymbolAddress((void**)&xhi, g_xhi);
        cudaGetSymbolAddress((void**)&xlo, g_xlo);
        cudaGetSymbolAddress((void**)&whi, g_w1hi);
        cudaGetSymbolAddress((void**)&wlo, g_w1lo);
        int nx4 = S_TOK * MDIM / 4;
        int nw4 = EDIM * MDIM * HDIM / 4;
        split_kernel<<<nx4 / 256, 256>>>(x, xhi, xlo, nx4);
        split_kernel<<<nw4 / 256, 256>>>(w1, whi, wlo, nw4);
    }
    w2s_kernel<<<(EDIM * HDIM + EDIM + 7) / 8, 256>>>(w2, b2);

    cudaFuncSetAttribute(moe_gemm_mma,
                         cudaFuncAttributeMaxDynamicSharedMemorySize, GEMM_SMEM);
    moe_gemm_mma<<<dim3(HDIM / 128, CDIM / 128, EDIM), 256, GEMM_SMEM>>>(b1);

    combine_kernel<<<S_TOK / 256, 256>>>(out);
    lsm_kernel<<<4, 256>>>(out);
}

// round 4
// speedup vs baseline: 4.4381x; 2.0227x over previous
#include <cuda_runtime.h>
#include <cuda_fp16.h>
#include <math.h>
#include <stdint.h>

#define S_TOK 8192
#define MDIM  1024
#define HDIM  2048
#define EDIM  8
#define CDIM  2048

// ---------------- scratch (device globals; no allocation) ----------------
__device__ int   g_topi[S_TOK * 2];
__device__ float g_gate[S_TOK * 2];
__device__ int   g_dexp[S_TOK * 2];
__device__ int   g_dpos[S_TOK * 2];
__device__ float g_dg  [S_TOK * 2];
__device__ int   g_src [EDIM * CDIM];
__device__ float g_z   [EDIM * CDIM];
__device__ float g_w2s [EDIM * HDIM];
__device__ float g_b2s [EDIM];
// fp16 copies for MMA
__device__ __half g_xh [(size_t)S_TOK * MDIM];
__device__ __half g_w1h[(size_t)EDIM * MDIM * HDIM];

// ---------------- helpers -------------------------------------------------
__device__ __forceinline__ uint32_t smem_u32(const void* p) {
    uint32_t a;
    asm("{ .reg .u64 t; cvta.to.shared.u64 t, %1; cvt.u32.u64 %0, t; }"
        : "=r"(a) : "l"(p));
    return a;
}
#define CP_ASYNC(saddr, gptr) \
    asm volatile("cp.async.cg.shared.global [%0], [%1], 16;" \
        :: "r"(saddr), "l"(gptr) : "memory")
#define CP_ASYNC_Z(saddr, gptr, srcsz) \
    asm volatile("cp.async.cg.shared.global [%0], [%1], 16, %2;" \
        :: "r"(saddr), "l"(gptr), "r"(srcsz) : "memory")
#define CP_COMMIT() asm volatile("cp.async.commit_group;" ::: "memory")
#define CP_WAIT(n)  asm volatile("cp.async.wait_group %0;" :: "n"(n) : "memory")

#define LDSM4(r, addr) \
    asm volatile("ldmatrix.sync.aligned.m8n8.x4.shared.b16 {%0,%1,%2,%3}, [%4];" \
        : "=r"((r)[0]), "=r"((r)[1]), "=r"((r)[2]), "=r"((r)[3]) : "r"(addr))
#define LDSM4T(r, addr) \
    asm volatile("ldmatrix.sync.aligned.m8n8.x4.trans.shared.b16 {%0,%1,%2,%3}, [%4];" \
        : "=r"((r)[0]), "=r"((r)[1]), "=r"((r)[2]), "=r"((r)[3]) : "r"(addr))
#define MMA_F16(d, a, b0, b1) \
    asm volatile("mma.sync.aligned.m16n8k16.row.col.f32.f16.f16.f32 " \
        "{%0,%1,%2,%3}, {%4,%5,%6,%7}, {%8,%9}, {%0,%1,%2,%3};" \
        : "+f"((d)[0]), "+f"((d)[1]), "+f"((d)[2]), "+f"((d)[3]) \
        : "r"((a)[0]), "r"((a)[1]), "r"((a)[2]), "r"((a)[3]), "r"(b0), "r"(b1))

// ---------------- 1. router -----------------------------------------------
__global__ void routing_kernel(const float* __restrict__ x,
                               const float* __restrict__ wg) {
    int warp = (blockIdx.x * blockDim.x + threadIdx.x) >> 5;
    int lane = threadIdx.x & 31;
    if (warp >= S_TOK) return;
    const float* xr = x + (size_t)warp * MDIM;
    float acc[8];
#pragma unroll
    for (int e = 0; e < 8; e++) acc[e] = 0.f;
    for (int m = lane; m < MDIM; m += 32) {
        float xv = xr[m];
        const float* wr = wg + m * 8;
        float4 w0 = *(const float4*)(wr);
        float4 w1 = *(const float4*)(wr + 4);
        acc[0] += xv * w0.x; acc[1] += xv * w0.y;
        acc[2] += xv * w0.z; acc[3] += xv * w0.w;
        acc[4] += xv * w1.x; acc[5] += xv * w1.y;
        acc[6] += xv * w1.z; acc[7] += xv * w1.w;
    }
#pragma unroll
    for (int off = 16; off > 0; off >>= 1)
#pragma unroll
        for (int e = 0; e < 8; e++)
            acc[e] += __shfl_down_sync(0xffffffffu, acc[e], off);
    if (lane == 0) {
        float mx = acc[0];
#pragma unroll
        for (int e = 1; e < 8; e++) mx = fmaxf(mx, acc[e]);
        float sc[8], s = 0.f;
#pragma unroll
        for (int e = 0; e < 8; e++) { sc[e] = expf(acc[e] - mx); s += sc[e]; }
        float inv = 1.f / s;
#pragma unroll
        for (int e = 0; e < 8; e++) sc[e] *= inv;
        int i0 = 0;
#pragma unroll
        for (int e = 1; e < 8; e++) if (sc[e] > sc[i0]) i0 = e;
        int i1 = -1;
#pragma unroll
        for (int e = 0; e < 8; e++) {
            if (e == i0) continue;
            if (i1 < 0 || sc[e] > sc[i1]) i1 = e;
        }
        float v0 = sc[i0], v1 = sc[i1];
        float den = 1.f / (v0 + v1 + 1e-9f);
        g_topi[warp * 2 + 0] = i0;
        g_topi[warp * 2 + 1] = i1;
        g_gate[warp * 2 + 0] = v0 * den;
        g_gate[warp * 2 + 1] = v1 * den;
    }
}

// ---------------- 2. ordered scan -----------------------------------------
__global__ void scan_kernel() {
    __shared__ int h0[256][8];
    __shared__ int h1[256][8];
    __shared__ int tot0[8];
    int t = threadIdx.x;
    for (int i = t; i < EDIM * CDIM; i += 256) { g_src[i] = -1; g_z[i] = 0.f; }

    int c0[8], c1[8];
#pragma unroll
    for (int e = 0; e < 8; e++) { c0[e] = 0; c1[e] = 0; }
    int base = t * 32;
    for (int k = 0; k < 32; k++) {
        int s = base + k;
        c0[g_topi[2 * s + 0]]++;
        c1[g_topi[2 * s + 1]]++;
    }
#pragma unroll
    for (int e = 0; e < 8; e++) { h0[t][e] = c0[e]; h1[t][e] = c1[e]; }
    __syncthreads();
    if (t < 16) {
        int e = t & 7, which = t >> 3;
        int run = 0;
        if (which == 0) {
            for (int i = 0; i < 256; i++) { int v = h0[i][e]; h0[i][e] = run; run += v; }
            tot0[e] = run;
        } else {
            for (int i = 0; i < 256; i++) { int v = h1[i][e]; h1[i][e] = run; run += v; }
        }
    }
    __syncthreads();
#pragma unroll
    for (int e = 0; e < 8; e++) { c0[e] = h0[t][e]; c1[e] = h1[t][e] + tot0[e]; }
    for (int k = 0; k < 32; k++) {
        int s = base + k;
        {
            int e = g_topi[2 * s + 0];
            int pos = c0[e]++;
            int keep = (pos < CDIM);
            int posc = keep ? pos : (CDIM - 1);
            g_dexp[2 * s + 0] = e;
            g_dpos[2 * s + 0] = posc;
            g_dg  [2 * s + 0] = keep ? g_gate[2 * s + 0] : 0.f;
            if (keep) g_src[e * CDIM + posc] = s;
        }
        {
            int e = g_topi[2 * s + 1];
            int pos = c1[e]++;
            int keep = (pos < CDIM);
            int posc = keep ? pos : (CDIM - 1);
            g_dexp[2 * s + 1] = e;
            g_dpos[2 * s + 1] = posc;
            g_dg  [2 * s + 1] = keep ? g_gate[2 * s + 1] : 0.f;
            if (keep) g_src[e * CDIM + posc] = s;
        }
    }
}

// ---------------- 3. w2s / b2s reductions ---------------------------------
__global__ void w2s_kernel(const float* __restrict__ w2,
                           const float* __restrict__ b2) {
    int warp = (blockIdx.x * blockDim.x + threadIdx.x) >> 5;
    int lane = threadIdx.x & 31;
    if (warp < EDIM * HDIM) {
        const float4* r = (const float4*)(w2 + (size_t)warp * MDIM);
        float s = 0.f;
        for (int m = lane; m < MDIM / 4; m += 32) {
            float4 v = r[m];
            s += v.x + v.y + v.z + v.w;
        }
#pragma unroll
        for (int off = 16; off > 0; off >>= 1) s += __shfl_down_sync(0xffffffffu, s, off);
        if (lane == 0) g_w2s[warp] = s;
    } else if (warp < EDIM * HDIM + EDIM) {
        int e = warp - EDIM * HDIM;
        const float4* r = (const float4*)(b2 + (size_t)e * MDIM);
        float s = 0.f;
        for (int m = lane; m < MDIM / 4; m += 32) {
            float4 v = r[m];
            s += v.x + v.y + v.z + v.w;
        }
#pragma unroll
        for (int off = 16; off > 0; off >>= 1) s += __shfl_down_sync(0xffffffffu, s, off);
        if (lane == 0) g_b2s[e] = s;
    }
}

// ---------------- 3b. fp32 -> fp16 convert --------------------------------
__global__ void tohalf_kernel(const float* __restrict__ src,
                              __half* __restrict__ dst, int n4) {
    int i = blockIdx.x * blockDim.x + threadIdx.x;
    if (i >= n4) return;
    float4 v = ((const float4*)src)[i];
    __half2 h01 = __floats2half2_rn(v.x, v.y);
    __half2 h23 = __floats2half2_rn(v.z, v.w);
    ((uint2*)dst)[i] = make_uint2(*(uint32_t*)&h01, *(uint32_t*)&h23);
}

// ---------------- 4. fp16 mma.sync fused GEMM -----------------------------
// CTA tile 128(C) x 128(H), BK=32, 4-stage cp.async pipeline.
// A rows padded to 80B (5 mod 8 banks -> ldmatrix conflict-free);
// B k-rows 256B with XOR-8 16B-unit swizzle.
#define NS   4
#define AH   0
#define BH   10240
#define STG  18432
#define GEMM_SMEM (NS * STG)

__global__ __launch_bounds__(256, 2)
void moe_gemm_fp16(const float* __restrict__ b1) {
    extern __shared__ char smem[];
    __shared__ int   rowsrc[128];
    __shared__ float b1s[128];
    __shared__ float w2ss[128];

    const int tid  = threadIdx.x;
    const int lane = tid & 31;
    const int wid  = tid >> 5;
    const int e  = blockIdx.z;
    const int cb = blockIdx.y * 128;
    const int nb = blockIdx.x * 128;

    if (tid < 128) {
        rowsrc[tid] = g_src[e * CDIM + cb + tid];
        b1s[tid]  = b1[e * HDIM + nb + tid];
        w2ss[tid] = g_w2s[e * HDIM + nb + tid];
    }
    __syncthreads();
    const uint32_t sb = smem_u32(smem);

    // ---- cp.async assignments ----
    // A: thread covers rows ar, ar+64; 16B unit au (k-cols au*8..au*8+7)
    const int ar = tid >> 2, au = tid & 3;
    const int s0 = rowsrc[ar], s1 = rowsrc[ar + 64];
    const uint32_t sz0 = (s0 >= 0) ? 16u : 0u;
    const uint32_t sz1 = (s1 >= 0) ? 16u : 0u;
    const char* gx0 = (const char*)g_xh + ((size_t)(s0 < 0 ? 0 : s0) * MDIM + au * 8) * 2;
    const char* gx1 = (const char*)g_xh + ((size_t)(s1 < 0 ? 0 : s1) * MDIM + au * 8) * 2;
    const uint32_t aoff0 = (uint32_t)(ar * 80 + au * 16);
    const uint32_t aoff1 = (uint32_t)((ar + 64) * 80 + au * 16);
    // B: thread covers k-rows br, br+16; unit bu (n-cols bu*8..bu*8+7)
    const int br = tid >> 4, bu = tid & 15;
    const char* gb = (const char*)g_w1h + (((size_t)e * MDIM) * HDIM + nb + bu * 8) * 2;
    const uint32_t sB0 = (uint32_t)(br * 256 + ((bu ^ (br & 7)) << 4));
    const uint32_t sB1 = sB0 + 16 * 256;

#define LOAD_STAGE(i) do {                                                    \
    const int _k0 = (i) * 32;                                                 \
    const uint32_t _st = sb + ((i) % NS) * STG;                               \
    CP_ASYNC_Z(_st + AH + aoff0, gx0 + _k0 * 2, sz0);                         \
    CP_ASYNC_Z(_st + AH + aoff1, gx1 + _k0 * 2, sz1);                         \
    const size_t _g = (size_t)(_k0 + br) * (HDIM * 2);                        \
    CP_ASYNC(_st + BH + sB0, gb + _g);                                        \
    CP_ASYNC(_st + BH + sB1, gb + _g + (size_t)16 * HDIM * 2);                \
    CP_COMMIT();                                                              \
} while (0)

    // ---- mma thread geometry ----
    const int m0 = (wid & 1) * 64;      // warp row block within CTA
    const int n0 = (wid >> 1) * 32;     // warp col block
    const uint32_t a_l = (uint32_t)((m0 + (lane & 15)) * 80 + ((lane >> 4) & 1) * 16);
    const int krow = lane & 15;
    const int un0  = (n0 >> 3) + (lane >> 4);
    const uint32_t b_row = (uint32_t)(krow * 256);
    const uint32_t bcol0 = (uint32_t)(((un0 + 0) ^ (krow & 7)) << 4);
    const uint32_t bcol1 = (uint32_t)(((un0 + 2) ^ (krow & 7)) << 4);

    float acc[4][4][4];
#pragma unroll
    for (int mi = 0; mi < 4; mi++)
#pragma unroll
        for (int nj = 0; nj < 4; nj++)
#pragma unroll
            for (int q = 0; q < 4; q++) acc[mi][nj][q] = 0.f;

    LOAD_STAGE(0);
    LOAD_STAGE(1);
    LOAD_STAGE(2);

    for (int i = 0; i < 32; i++) {
        CP_WAIT(2);
        __syncthreads();
        if (i + 3 < 32) LOAD_STAGE(i + 3); else CP_COMMIT();

        const uint32_t st = sb + (i % NS) * STG;
        const uint32_t ab = st + AH + a_l;
        const uint32_t bb = st + BH + b_row;
#pragma unroll
        for (int kk = 0; kk < 2; kk++) {
            uint32_t a[4][4], b[2][4];
#pragma unroll
            for (int mi = 0; mi < 4; mi++)
                LDSM4(a[mi], ab + mi * (16 * 80) + kk * 32);
            {
                uint32_t kb = (uint32_t)(kk * 16 * 256);
                LDSM4T(b[0], bb + kb + bcol0);
                LDSM4T(b[1], bb + kb + bcol1);
            }
#pragma unroll
            for (int mi = 0; mi < 4; mi++)
#pragma unroll
                for (int nj = 0; nj < 2; nj++) {
                    MMA_F16(acc[mi][nj * 2 + 0], a[mi], b[nj][0], b[nj][1]);
                    MMA_F16(acc[mi][nj * 2 + 1], a[mi], b[nj][2], b[nj][3]);
                }
        }
    }

    // ---- fused epilogue: relu(+b1) . w2s, reduce, atomicAdd into g_z ----
    const int rr = lane >> 2;
    const int cc = (lane & 3) * 2;
#pragma unroll
    for (int mi = 0; mi < 4; mi++) {
        float pl = 0.f, ph = 0.f;
#pragma unroll
        for (int nj = 0; nj < 4; nj++) {
            int col = n0 + nj * 8 + cc;
            float w0 = w2ss[col], w1v = w2ss[col + 1];
            float bb0 = b1s[col], bb1 = b1s[col + 1];
            pl += fmaxf(acc[mi][nj][0] + bb0, 0.f) * w0
                + fmaxf(acc[mi][nj][1] + bb1, 0.f) * w1v;
            ph += fmaxf(acc[mi][nj][2] + bb0, 0.f) * w0
                + fmaxf(acc[mi][nj][3] + bb1, 0.f) * w1v;
        }
        pl += __shfl_xor_sync(0xffffffffu, pl, 1);
        pl += __shfl_xor_sync(0xffffffffu, pl, 2);
        ph += __shfl_xor_sync(0xffffffffu, ph, 1);
        ph += __shfl_xor_sync(0xffffffffu, ph, 2);
        if ((lane & 3) == 0) {
            int row = cb + m0 + mi * 16 + rr;
            atomicAdd(&g_z[e * CDIM + row], pl);
            atomicAdd(&g_z[e * CDIM + row + 8], ph);
        }
    }
#undef LOAD_STAGE
}

// ---------------- 5. combine ----------------------------------------------
__global__ void combine_kernel(float* __restrict__ out) {
    int s = blockIdx.x * blockDim.x + threadIdx.x;
    if (s >= S_TOK) return;
    float v = 0.f;
#pragma unroll
    for (int j = 0; j < 2; j++) {
        int   e = g_dexp[2 * s + j];
        int   p = g_dpos[2 * s + j];
        float g = g_dg  [2 * s + j];
        v += g * (g_z[e * CDIM + p] + g_b2s[e]);
    }
    out[s] = v;
}

// ---------------- 6. log_softmax over T -----------------------------------
__global__ void lsm_kernel(float* __restrict__ out) {
    __shared__ float sred[256];
    int t = threadIdx.x;
    float* v = out + (size_t)blockIdx.x * 2048;
    float mx = -1e30f;
    for (int i = t; i < 2048; i += 256) mx = fmaxf(mx, v[i]);
    sred[t] = mx; __syncthreads();
    for (int o = 128; o > 0; o >>= 1) {
        if (t < o) sred[t] = fmaxf(sred[t], sred[t + o]);
        __syncthreads();
    }
    mx = sred[0]; __syncthreads();
    float sm = 0.f;
    for (int i = t; i < 2048; i += 256) sm += expf(v[i] - mx);
    sred[t] = sm; __syncthreads();
    for (int o = 128; o > 0; o >>= 1) {
        if (t < o) sred[t] += sred[t + o];
        __syncthreads();
    }
    float lse = mx + logf(sred[0]);
    for (int i = t; i < 2048; i += 256) v[i] = v[i] - lse;
}

// ---------------- launch ---------------------------------------------------
extern "C" void kernel_launch(void* const* d_in, const int* in_sizes, int n_in,
                              void* d_out, int out_size) {
    const float* x  = (const float*)d_in[0];
    const float* wg = (const float*)d_in[1];
    const float* w1 = (const float*)d_in[2];
    const float* b1 = (const float*)d_in[3];
    const float* w2 = (const float*)d_in[4];
    const float* b2 = (const float*)d_in[5];
    float* out = (float*)d_out;

    routing_kernel<<<S_TOK / 8, 256>>>(x, wg);
    scan_kernel<<<1, 256>>>();

    {   // fp32 -> fp16 conversions
        __half *xh, *wh;
        cudaGetSymbolAddress((void**)&xh, g_xh);
        cudaGetSymbolAddress((void**)&wh, g_w1h);
        int nx4 = S_TOK * MDIM / 4;
        int nw4 = EDIM * MDIM * HDIM / 4;
        tohalf_kernel<<<nx4 / 256, 256>>>(x, xh, nx4);
        tohalf_kernel<<<nw4 / 256, 256>>>(w1, wh, nw4);
    }
    w2s_kernel<<<(EDIM * HDIM + EDIM + 7) / 8, 256>>>(w2, b2);

    cudaFuncSetAttribute(moe_gemm_fp16,
                         cudaFuncAttributeMaxDynamicSharedMemorySize, GEMM_SMEM);
    moe_gemm_fp16<<<dim3(HDIM / 128, CDIM / 128, EDIM), 256, GEMM_SMEM>>>(b1);

    combine_kernel<<<S_TOK / 256, 256>>>(out);
    lsm_kernel<<<4, 256>>>(out);
}